// round 4
// baseline (speedup 1.0000x reference)
#include <cuda_runtime.h>
#include <cstdint>

// [B, 9, 5, 5] float32, 225 floats (900 B) per batch.
// Persistent 1-warp CTAs, double-buffered cp.async.bulk pipeline over
// 32-batch segments (28800 B each, 16B-aligned).
// Arithmetic replicates the JAX reference op-for-op (IEEE div, unfused mul/add)
// so the LU chain's ulp-amplification has nothing to amplify.
constexpr int NB = 32;
constexpr int THREADS = 32;
constexpr int BATCH_FLOATS = 225;
constexpr int SEG_FLOATS = NB * BATCH_FLOATS;   // 7200
constexpr int SEG_BYTES = SEG_FLOATS * 4;       // 28800
constexpr int SMEM_BYTES = 128 + 2 * SEG_BYTES; // 57728 -> 3 CTAs/SM
constexpr int MAX_CTAS = 456;

__device__ __forceinline__ uint32_t s2u(const void* p) {
    return (uint32_t)__cvta_generic_to_shared(p);
}

// Unpivoted 5x5 LU in registers, reference-exact arithmetic:
//   col  = a[i][k] / a[k][k]            (IEEE correctly-rounded division)
//   a[i][j] = a[i][j] + (-(col*a[k][j])) (separate mul and add, NO fma)
__device__ __forceinline__ void lu5(float* a) {
#pragma unroll
    for (int k = 0; k < 4; ++k) {
        const float piv = a[k * 5 + k];
#pragma unroll
        for (int i = k + 1; i < 5; ++i) {
            const float c = __fdiv_rn(a[i * 5 + k], piv);
            a[i * 5 + k] = c;
#pragma unroll
            for (int j = k + 1; j < 5; ++j)
                a[i * 5 + j] = __fadd_rn(a[i * 5 + j], -__fmul_rn(c, a[k * 5 + j]));
        }
    }
}

__device__ __forceinline__ void load_blk(const float* m, int blk, float* a) {
    const float* p = m + blk * 25;
#pragma unroll
    for (int i = 0; i < 25; ++i) a[i] = p[i];
}

__device__ __forceinline__ void store_blk(float* m, int blk, const float* a) {
    float* p = m + blk * 25;
#pragma unroll
    for (int i = 0; i < 25; ++i) p[i] = a[i];
}

// Full per-batch factorization: 8 LUs + fill-in chain (scatter-add order
// matches the reference's duplicate-index accumulation order).
__device__ __forceinline__ void factor_batch(float* m) {
    float a[25];

    load_blk(m, 0, a); lu5(a); store_blk(m, 0, a);
    const float s0 = a[6];

    load_blk(m, 1, a); lu5(a); store_blk(m, 1, a);
    const float s1 = a[6];

    load_blk(m, 2, a); lu5(a); store_blk(m, 2, a);
    const float c22 = a[12], c23 = a[13], c32 = a[17], c33 = a[18];

    load_blk(m, 5, a); lu5(a); store_blk(m, 5, a);
    const float s5 = a[6];

    load_blk(m, 6, a); lu5(a); store_blk(m, 6, a);
    const float d33 = a[18], d34 = a[19], d43 = a[23], d44 = a[24];

    // Block 4: passthrough (already staged).

    load_blk(m, 3, a);
    a[0] = __fadd_rn(__fadd_rn(a[0], -s1), -c22);  // dup-dst order: A1 then A2
    a[1] = __fadd_rn(a[1], -c23);
    a[5] = __fadd_rn(a[5], -c32);
    a[6] = __fadd_rn(a[6], -c33);
    lu5(a); store_blk(m, 3, a);
    const float t3 = a[6];

    load_blk(m, 7, a);
    a[0] = __fadd_rn(__fadd_rn(a[0], -s5), -d33);  // A5 then A6
    a[1] = __fadd_rn(a[1], -d34);
    a[5] = __fadd_rn(a[5], -d43);
    a[6] = __fadd_rn(a[6], -d44);
    lu5(a); store_blk(m, 7, a);
    const float t7 = a[6];

    load_blk(m, 8, a);
    a[0] = __fadd_rn(__fadd_rn(__fadd_rn(a[0], -s0), -t3), -t7);  // A0, A3, A7
    lu5(a); store_blk(m, 8, a);
}

#define MBAR_WAIT(addr, parity) do {                                          \
    asm volatile(                                                             \
        "{\n\t.reg .pred p;\n\t"                                              \
        "WL%=:\n\t"                                                           \
        "mbarrier.try_wait.parity.acquire.cta.shared::cta.b64 p, [%0], %1;\n\t" \
        "@!p bra WL%=;\n\t}"                                                  \
        :: "r"(addr), "r"(parity) : "memory");                                \
} while (0)

extern __shared__ float smem[];

__global__ void __launch_bounds__(THREADS)
lu_pipe_kernel(const float* __restrict__ in, float* __restrict__ out, int nseg) {
    // Layout: [0,16) mbarriers, buffers at byte 128 and 128+SEG_BYTES.
    uint64_t* mbar = (uint64_t*)smem;
    float* buf0 = smem + 32;
    float* buf1 = smem + 32 + SEG_FLOATS;
    const int tid = threadIdx.x;
    const uint32_t mb[2] = { s2u(&mbar[0]), s2u(&mbar[1]) };
    const uint32_t bufaddr[2] = { s2u(buf0), s2u(buf1) };
    float* const bufp[2] = { buf0, buf1 };

    if (tid == 0) {
        asm volatile("mbarrier.init.shared::cta.b64 [%0], 1;" :: "r"(mb[0]));
        asm volatile("mbarrier.init.shared::cta.b64 [%0], 1;" :: "r"(mb[1]));
    }
    __syncwarp();

    long long s = blockIdx.x;

    // Prologue: start load of first segment into buffer 0.
    if (tid == 0 && s < nseg) {
        asm volatile("mbarrier.arrive.expect_tx.shared::cta.b64 _, [%0], %1;"
                     :: "r"(mb[0]), "r"(SEG_BYTES));
        asm volatile(
            "cp.async.bulk.shared::cta.global.mbarrier::complete_tx::bytes "
            "[%0], [%1], %2, [%3];"
            :: "r"(bufaddr[0]), "l"(in + s * SEG_FLOATS), "r"(SEG_BYTES),
               "r"(mb[0]) : "memory");
    }

    int ph[2] = { 0, 0 };
    int iter = 0;
    for (; s < nseg; s += gridDim.x, ++iter) {
        const int cur = iter & 1;
        const int nxt = cur ^ 1;
        const long long ns = s + gridDim.x;

        // Prefetch next segment into the other buffer. Its previous store
        // (committed one iteration ago) must finish reading smem first.
        if (tid == 0 && ns < nseg) {
            asm volatile("cp.async.bulk.wait_group.read 0;" ::: "memory");
            asm volatile("mbarrier.arrive.expect_tx.shared::cta.b64 _, [%0], %1;"
                         :: "r"(mb[nxt]), "r"(SEG_BYTES));
            asm volatile(
                "cp.async.bulk.shared::cta.global.mbarrier::complete_tx::bytes "
                "[%0], [%1], %2, [%3];"
                :: "r"(bufaddr[nxt]), "l"(in + ns * SEG_FLOATS), "r"(SEG_BYTES),
                   "r"(mb[nxt]) : "memory");
        }

        // Wait for current segment's data.
        MBAR_WAIT(mb[cur], ph[cur]);
        ph[cur] ^= 1;
        __syncwarp();

        // One thread per batch; smem stride 225 == 1 (mod 32): conflict-free.
        factor_batch(bufp[cur] + tid * BATCH_FLOATS);

        __syncwarp();
        asm volatile("fence.proxy.async.shared::cta;" ::: "memory");
        __syncwarp();

        // Async store of the finished segment; don't wait.
        if (tid == 0) {
            asm volatile(
                "cp.async.bulk.global.shared::cta.bulk_group [%0], [%1], %2;"
                :: "l"(out + s * SEG_FLOATS), "r"(bufaddr[cur]), "r"(SEG_BYTES)
                : "memory");
            asm volatile("cp.async.bulk.commit_group;" ::: "memory");
        }
    }

    // Drain pending bulk-store smem reads before CTA exit.
    if (tid == 0)
        asm volatile("cp.async.bulk.wait_group.read 0;" ::: "memory");
}

// Tail path for nbatch % NB != 0 (never taken for B=524288; kept for safety).
__global__ void lu_tail_kernel(const float* __restrict__ in,
                               float* __restrict__ out, int start, int nbatch) {
    const int b = start + blockIdx.x * blockDim.x + threadIdx.x;
    if (b >= nbatch) return;
    float m[BATCH_FLOATS];
    const float* src = in + (long long)b * BATCH_FLOATS;
#pragma unroll 1
    for (int i = 0; i < BATCH_FLOATS; ++i) m[i] = src[i];
    factor_batch(m);
    float* dst = out + (long long)b * BATCH_FLOATS;
#pragma unroll 1
    for (int i = 0; i < BATCH_FLOATS; ++i) dst[i] = m[i];
}

extern "C" void kernel_launch(void* const* d_in, const int* in_sizes, int n_in,
                              void* d_out, int out_size) {
    const float* in = (const float*)d_in[0];
    float* out = (float*)d_out;
    const int nbatch = in_sizes[0] / BATCH_FLOATS;
    const int nseg = nbatch / NB;
    const int rem = nbatch - nseg * NB;

    static bool attr_set = false;  // idempotent opt-in to >48KB dynamic smem
    if (!attr_set) {
        cudaFuncSetAttribute(lu_pipe_kernel,
                             cudaFuncAttributeMaxDynamicSharedMemorySize, SMEM_BYTES);
        attr_set = true;
    }

    if (nseg > 0) {
        const int grid = nseg < MAX_CTAS ? nseg : MAX_CTAS;
        lu_pipe_kernel<<<grid, THREADS, SMEM_BYTES>>>(in, out, nseg);
    }
    if (rem > 0) {
        lu_tail_kernel<<<1, ((rem + 31) / 32) * 32>>>(in, out, nseg * NB, nbatch);
    }
}

// round 5
// speedup vs baseline: 1.6541x; 1.6541x over previous
#include <cuda_runtime.h>
#include <cstdint>

// [B, 9, 5, 5] float32, 225 floats (900 B) per batch.
// Persistent 1-warp CTAs, double-buffered cp.async.bulk pipeline over
// 16-batch segments (14400 B each). 2 buffers = 28.9 KB/CTA -> 7 CTAs/SM.
// Arithmetic is the frozen round-1/2 sequence (rcp.approx + fmaf): measured
// rel_err 4.918e-4, the best of all variants tried. Do not alter.
constexpr int NB = 16;
constexpr int THREADS = 32;
constexpr int BATCH_FLOATS = 225;
constexpr int SEG_FLOATS = NB * BATCH_FLOATS;   // 3600
constexpr int SEG_BYTES = SEG_FLOATS * 4;       // 14400
constexpr int SMEM_BYTES = 128 + 2 * SEG_BYTES; // 28928 -> 7 CTAs/SM
constexpr int MAX_CTAS = 1064;                  // 7 per SM * 152 SMs

__device__ __forceinline__ uint32_t s2u(const void* p) {
    return (uint32_t)__cvta_generic_to_shared(p);
}

__device__ __forceinline__ float rcp_fast(float x) {
    float r;
    asm("rcp.approx.f32 %0, %1;" : "=f"(r) : "f"(x));
    return r;
}

// Unpivoted 5x5 LU fully in registers — FROZEN arithmetic (round 1/2).
__device__ __forceinline__ void lu5(float* a) {
#pragma unroll
    for (int k = 0; k < 4; ++k) {
        const float rinv = rcp_fast(a[k * 5 + k]);
#pragma unroll
        for (int i = k + 1; i < 5; ++i) {
            const float c = a[i * 5 + k] * rinv;
            a[i * 5 + k] = c;
#pragma unroll
            for (int j = k + 1; j < 5; ++j)
                a[i * 5 + j] = fmaf(-c, a[k * 5 + j], a[i * 5 + j]);
        }
    }
}

__device__ __forceinline__ void load_blk(const float* m, int blk, float* a) {
    const float* p = m + blk * 25;
#pragma unroll
    for (int i = 0; i < 25; ++i) a[i] = p[i];
}

__device__ __forceinline__ void store_blk(float* m, int blk, const float* a) {
    float* p = m + blk * 25;
#pragma unroll
    for (int i = 0; i < 25; ++i) p[i] = a[i];
}

// Full per-batch factorization — FROZEN op sequence (round 1/2).
__device__ __forceinline__ void factor_batch(float* m) {
    float a[25];

    load_blk(m, 0, a); lu5(a); store_blk(m, 0, a);
    const float s0 = a[6];

    load_blk(m, 1, a); lu5(a); store_blk(m, 1, a);
    const float s1 = a[6];

    load_blk(m, 2, a); lu5(a); store_blk(m, 2, a);
    const float c22 = a[12], c23 = a[13], c32 = a[17], c33 = a[18];

    load_blk(m, 5, a); lu5(a); store_blk(m, 5, a);
    const float s5 = a[6];

    load_blk(m, 6, a); lu5(a); store_blk(m, 6, a);
    const float d33 = a[18], d34 = a[19], d43 = a[23], d44 = a[24];

    // Block 4: passthrough (already staged).

    load_blk(m, 3, a);
    a[0] = a[0] - s1 - c22;
    a[1] -= c23;
    a[5] -= c32;
    a[6] -= c33;
    lu5(a); store_blk(m, 3, a);
    const float t3 = a[6];

    load_blk(m, 7, a);
    a[0] = a[0] - s5 - d33;
    a[1] -= d34;
    a[5] -= d43;
    a[6] -= d44;
    lu5(a); store_blk(m, 7, a);
    const float t7 = a[6];

    load_blk(m, 8, a);
    a[0] = a[0] - s0 - t3 - t7;
    lu5(a); store_blk(m, 8, a);
}

#define MBAR_WAIT(addr, parity) do {                                          \
    asm volatile(                                                             \
        "{\n\t.reg .pred p;\n\t"                                              \
        "WL%=:\n\t"                                                           \
        "mbarrier.try_wait.parity.acquire.cta.shared::cta.b64 p, [%0], %1;\n\t" \
        "@!p bra WL%=;\n\t}"                                                  \
        :: "r"(addr), "r"(parity) : "memory");                                \
} while (0)

extern __shared__ float smem[];

__global__ void __launch_bounds__(THREADS)
lu_pipe_kernel(const float* __restrict__ in, float* __restrict__ out, int nseg) {
    // Layout: [0,16) mbarriers (128B pad), buffers at 128 and 128+SEG_BYTES.
    uint64_t* mbar = (uint64_t*)smem;
    float* buf0 = smem + 32;
    float* buf1 = smem + 32 + SEG_FLOATS;
    const int tid = threadIdx.x;
    const uint32_t mb[2] = { s2u(&mbar[0]), s2u(&mbar[1]) };
    const uint32_t bufaddr[2] = { s2u(buf0), s2u(buf1) };
    float* const bufp[2] = { buf0, buf1 };

    if (tid == 0) {
        asm volatile("mbarrier.init.shared::cta.b64 [%0], 1;" :: "r"(mb[0]));
        asm volatile("mbarrier.init.shared::cta.b64 [%0], 1;" :: "r"(mb[1]));
    }
    __syncwarp();

    long long s = blockIdx.x;

    // Prologue: start load of first segment into buffer 0.
    if (tid == 0 && s < nseg) {
        asm volatile("mbarrier.arrive.expect_tx.shared::cta.b64 _, [%0], %1;"
                     :: "r"(mb[0]), "r"(SEG_BYTES));
        asm volatile(
            "cp.async.bulk.shared::cta.global.mbarrier::complete_tx::bytes "
            "[%0], [%1], %2, [%3];"
            :: "r"(bufaddr[0]), "l"(in + s * SEG_FLOATS), "r"(SEG_BYTES),
               "r"(mb[0]) : "memory");
    }

    int ph[2] = { 0, 0 };
    int iter = 0;
    for (; s < nseg; s += gridDim.x, ++iter) {
        const int cur = iter & 1;
        const int nxt = cur ^ 1;
        const long long ns = s + gridDim.x;

        // Prefetch next segment into the other buffer. Its previous store
        // (committed one iteration ago) must finish reading smem first.
        if (tid == 0 && ns < nseg) {
            asm volatile("cp.async.bulk.wait_group.read 0;" ::: "memory");
            asm volatile("mbarrier.arrive.expect_tx.shared::cta.b64 _, [%0], %1;"
                         :: "r"(mb[nxt]), "r"(SEG_BYTES));
            asm volatile(
                "cp.async.bulk.shared::cta.global.mbarrier::complete_tx::bytes "
                "[%0], [%1], %2, [%3];"
                :: "r"(bufaddr[nxt]), "l"(in + ns * SEG_FLOATS), "r"(SEG_BYTES),
                   "r"(mb[nxt]) : "memory");
        }

        // Wait for current segment's data.
        MBAR_WAIT(mb[cur], ph[cur]);
        ph[cur] ^= 1;
        __syncwarp();

        // One thread per batch (threads 0..NB-1). smem stride 225 == 1 (mod 32):
        // conflict-free.
        if (tid < NB)
            factor_batch(bufp[cur] + tid * BATCH_FLOATS);

        __syncwarp();
        asm volatile("fence.proxy.async.shared::cta;" ::: "memory");
        __syncwarp();

        // Async store of the finished segment; don't wait.
        if (tid == 0) {
            asm volatile(
                "cp.async.bulk.global.shared::cta.bulk_group [%0], [%1], %2;"
                :: "l"(out + s * SEG_FLOATS), "r"(bufaddr[cur]), "r"(SEG_BYTES)
                : "memory");
            asm volatile("cp.async.bulk.commit_group;" ::: "memory");
        }
    }

    // Drain pending bulk-store smem reads before CTA exit.
    if (tid == 0)
        asm volatile("cp.async.bulk.wait_group.read 0;" ::: "memory");
}

// Tail path for nbatch % NB != 0 (never taken for B=524288; kept for safety).
__global__ void lu_tail_kernel(const float* __restrict__ in,
                               float* __restrict__ out, int start, int nbatch) {
    const int b = start + blockIdx.x * blockDim.x + threadIdx.x;
    if (b >= nbatch) return;
    float m[BATCH_FLOATS];
    const float* src = in + (long long)b * BATCH_FLOATS;
#pragma unroll 1
    for (int i = 0; i < BATCH_FLOATS; ++i) m[i] = src[i];
    factor_batch(m);
    float* dst = out + (long long)b * BATCH_FLOATS;
#pragma unroll 1
    for (int i = 0; i < BATCH_FLOATS; ++i) dst[i] = m[i];
}

extern "C" void kernel_launch(void* const* d_in, const int* in_sizes, int n_in,
                              void* d_out, int out_size) {
    const float* in = (const float*)d_in[0];
    float* out = (float*)d_out;
    const int nbatch = in_sizes[0] / BATCH_FLOATS;
    const int nseg = nbatch / NB;
    const int rem = nbatch - nseg * NB;

    static bool attr_set = false;  // idempotent opt-in (cheap; graph-capture safe)
    if (!attr_set) {
        cudaFuncSetAttribute(lu_pipe_kernel,
                             cudaFuncAttributeMaxDynamicSharedMemorySize, SMEM_BYTES);
        attr_set = true;
    }

    if (nseg > 0) {
        const int grid = nseg < MAX_CTAS ? nseg : MAX_CTAS;
        lu_pipe_kernel<<<grid, THREADS, SMEM_BYTES>>>(in, out, nseg);
    }
    if (rem > 0) {
        lu_tail_kernel<<<1, ((rem + 31) / 32) * 32>>>(in, out, nseg * NB, nbatch);
    }
}